// round 11
// baseline (speedup 1.0000x reference)
#include <cuda_runtime.h>
#include <cuda_fp16.h>
#include <math.h>

#define GS   160
#define KD   128
#define NKS  16
#define FSCALE      262144.0f            // 2^18
#define INV_FSCALE  3.814697265625e-06f  // 2^-18

#define SPEC_GRID 608                    // 4 blocks/SM x 152 SMs (GB300)
#define NPMAX 131072
#define NBKT  4096

__device__ __half2 g_tmp_h[3][KD][GS][GS];     // [t][kd][a_k][b]
__device__ __half2 g_field_h[3][GS][GS][KD];   // [t][h][w][kd]

__device__ int            g_hist[NBKT];
__device__ int            g_cursor[NBKT];
__device__ unsigned short g_keybuf[NPMAX];
__device__ int            g_order[NPMAX];

// ---------------- packed f32x2 helpers (sm_103a) ----------------
typedef unsigned long long u64p;

__device__ __forceinline__ u64p pk2(float x, float y){
    u64p r; asm("mov.b64 %0, {%1, %2};" : "=l"(r) : "f"(x), "f"(y)); return r;
}
__device__ __forceinline__ void upk2(u64p p, float& x, float& y){
    asm("mov.b64 {%0, %1}, %2;" : "=f"(x), "=f"(y) : "l"(p));
}
__device__ __forceinline__ u64p swp2(u64p p){
    float x, y; upk2(p, x, y); return pk2(y, x);
}
__device__ __forceinline__ u64p fma2p(u64p a, u64p b, u64p c){
    u64p d; asm("fma.rn.f32x2 %0, %1, %2, %3;" : "=l"(d) : "l"(a), "l"(b), "l"(c)); return d;
}
__device__ __forceinline__ u64p mul2p(u64p a, u64p b){
    u64p d; asm("mul.rn.f32x2 %0, %1, %2;" : "=l"(d) : "l"(a), "l"(b)); return d;
}
__device__ __forceinline__ u64p add2p(u64p a, u64p b){
    u64p d; asm("add.rn.f32x2 %0, %1, %2;" : "=l"(d) : "l"(a), "l"(b)); return d;
}
__device__ __forceinline__ u64p cmulp(u64p T, u64p tc, u64p ts){
    return fma2p(swp2(T), ts, mul2p(T, tc));
}

struct Tw {
    u64p stc[5], sts[5], g2[5];
    u64p tac[4], tas[4];
    int  k1;
};

__device__ __forceinline__ float softplus_scale(const float* __restrict__ alpha_params){
    float a0 = alpha_params[0];
    float bx = 10.0f * a0;
    float alpha = (bx > 1.0f) ? a0 : (log1pf(expf(fminf(bx, 1.0f))) * 0.1f);
    return alpha * (1.0f / 25600.0f) * FSCALE;
}

__device__ __forceinline__ void make_tw(Tw &tw, int lane){
#pragma unroll
    for (int s = 0; s < 5; s++){
        int H = 16 >> s;
        float cv = 1.0f, sv = 0.0f, g = 1.0f;
        if (lane & H){
            int j = lane & (H - 1);
            sincospif((float)j / (float)H, &sv, &cv);
            g = -1.0f;
        }
        tw.stc[s] = pk2(cv, cv);
        tw.sts[s] = pk2(-sv, sv);
        tw.g2[s]  = pk2(g, g);
    }
    tw.k1 = (int)(__brev((unsigned)lane) >> 27);
#pragma unroll
    for (int r = 1; r < 5; r++){
        float sv, cv;
        sincospif((float)(lane * r) / 80.0f, &sv, &cv);
        tw.tac[r - 1] = pk2(cv, cv);
        tw.tas[r - 1] = pk2(-sv, sv);
    }
}

// Inverse-sign DFT-160 across a warp, stride-1 input mapping, packed f32x2.
__device__ __forceinline__ void fft160p(u64p v[5], u64p o[5], const Tw &tw, int lane){
    const float C1 =  0.30901699437494745f;
    const float C2 = -0.80901699437494734f;
    const float S1 =  0.95105651629515353f;
    const float S2 =  0.58778525229247314f;
    const u64p C1p  = pk2(C1, C1),  C2p = pk2(C2, C2);
    const u64p S1p  = pk2(S1, S1),  S2p = pk2(S2, S2);
    const u64p mS1p = pk2(-S1, -S1);
    const u64p NEG1 = pk2(-1.0f, -1.0f);
    const u64p PM   = pk2(-1.0f, 1.0f);
    const u64p MP   = pk2(1.0f, -1.0f);

    u64p s1 = add2p(v[1], v[4]);
    u64p d1 = fma2p(v[4], NEG1, v[1]);
    u64p s2 = add2p(v[2], v[3]);
    u64p d2 = fma2p(v[3], NEG1, v[2]);
    o[0] = add2p(v[0], add2p(s1, s2));
    u64p ua = fma2p(s2, C2p, fma2p(s1, C1p, v[0]));
    u64p ub = fma2p(s2, C1p, fma2p(s1, C2p, v[0]));
    u64p wa = fma2p(d2, S2p,  mul2p(d1, S1p));
    u64p wb = fma2p(d2, mS1p, mul2p(d1, S2p));
    u64p X1 = fma2p(swp2(wa), PM, ua);
    u64p X4 = fma2p(swp2(wa), MP, ua);
    u64p X2 = fma2p(swp2(wb), PM, ub);
    u64p X3 = fma2p(swp2(wb), MP, ub);
    o[1] = cmulp(X1, tw.tac[0], tw.tas[0]);
    o[2] = cmulp(X2, tw.tac[1], tw.tas[1]);
    o[3] = cmulp(X3, tw.tac[2], tw.tas[2]);
    o[4] = cmulp(X4, tw.tac[3], tw.tas[3]);

#pragma unroll
    for (int s = 0; s < 5; s++){
        int H = 16 >> s;
#pragma unroll
        for (int r = 0; r < 5; r++){
            float ox, oy; upk2(o[r], ox, oy);
            float px = __shfl_xor_sync(0xffffffffu, ox, H);
            float py = __shfl_xor_sync(0xffffffffu, oy, H);
            u64p T = fma2p(o[r], tw.g2[s], pk2(px, py));
            o[r] = cmulp(T, tw.stc[s], tw.sts[s]);
        }
    }
}

// Persistent pass 1: grid(SPEC_GRID) x 256. 1920 tiles (640 per tensor).
__global__ void __launch_bounds__(256)
pass1_kernel(const float* __restrict__ pur, const float* __restrict__ pui,
             const float* __restrict__ pvr, const float* __restrict__ pvi,
             const float* __restrict__ pwr, const float* __restrict__ pwi,
             const float* __restrict__ alpha_params)
{
    __shared__ char smbuf[48640];
    int wid  = threadIdx.x >> 5;
    int lane = threadIdx.x & 31;
    float scale = softplus_scale(alpha_params);

    Tw tw; make_tw(tw, lane);

#pragma unroll 1
    for (int tile = blockIdx.x; tile < 1920; tile += SPEC_GRID){
        int z  = tile / 640;
        int id = tile - z * 640;

        if (z < 2){
            int kd = id / 5;
            int bx = id - kd * 5;
            const float* re = (z == 0) ? pur : pvr;
            const float* im = (z == 0) ? pui : pvi;
            int k = kd >> 3, d = kd & 7;

            __half2* sm1 = (__half2*)smbuf;

#pragma unroll 1
            for (int r = 0; r < 4; r++){
                int rl = wid * 4 + r;
                int b  = bx * 32 + rl;
                int base = (z == 0) ? ((kd * GS + b) * GS)
                                    : (((k * GS + b) * 8 + d) * GS);
                u64p v[5], o[5];
#pragma unroll
                for (int j = 0; j < 5; j++){
                    int idx = base + lane + 32 * j;
                    v[j] = pk2(re[idx] * scale, im[idx] * scale);
                }
                fft160p(v, o, tw, lane);
#pragma unroll
                for (int r2 = 0; r2 < 5; r2++){
                    float x, y; upk2(o[r2], x, y);
                    sm1[(r2 + 5 * tw.k1) * 33 + rl] = __floats2half2_rn(x, y);
                }
            }
            __syncthreads();

#pragma unroll 1
            for (int idx = threadIdx.x; idx < GS * 8; idx += 256){
                int w = idx >> 3, g = idx & 7;
                const __half2* p = &sm1[w * 33 + g * 4];
                uint4 val;
                val.x = *(const unsigned*)&p[0];
                val.y = *(const unsigned*)&p[1];
                val.z = *(const unsigned*)&p[2];
                val.w = *(const unsigned*)&p[3];
                *(uint4*)&g_tmp_h[z][kd][w][bx * 32 + g * 4] = val;
            }
        } else {
            int k  = id / 40;
            int yb = id - k * 40;

            unsigned* smw  = (unsigned*)smbuf;
            __half2*  sm1w = (__half2*)(smbuf + 4 * 1440 * 4);

            {
                const float4* re4 = (const float4*)pwr;
                const float4* im4 = (const float4*)pwi;
                int y0 = yb * 4;
#pragma unroll 1
                for (int i = threadIdx.x; i < 1280; i += 256){
                    int X   = i >> 3;
                    int rem = i & 7;
                    int y   = rem >> 1;
                    int dg  = (rem & 1) * 4;
                    int gidx = ((k * GS + X) * GS + y0 + y) * 2 + (rem & 1);
                    float4 fr = re4[gidx];
                    float4 fi = im4[gidx];
                    unsigned* dst = &smw[y * 1440 + X * 9 + dg];
                    __half2 h0 = __floats2half2_rn(fr.x * scale, fi.x * scale);
                    __half2 h1 = __floats2half2_rn(fr.y * scale, fi.y * scale);
                    __half2 h2 = __floats2half2_rn(fr.z * scale, fi.z * scale);
                    __half2 h3 = __floats2half2_rn(fr.w * scale, fi.w * scale);
                    dst[0] = *(unsigned*)&h0;
                    dst[1] = *(unsigned*)&h1;
                    dst[2] = *(unsigned*)&h2;
                    dst[3] = *(unsigned*)&h3;
                }
            }
            __syncthreads();

#pragma unroll 1
            for (int yr = 0; yr < 4; yr++){
                u64p v[5], o[5];
#pragma unroll
                for (int j = 0; j < 5; j++){
                    unsigned u = smw[yr * 1440 + (lane + 32 * j) * 9 + wid];
                    float2 f = __half22float2(*(__half2*)&u);
                    v[j] = pk2(f.x, f.y);
                }
                fft160p(v, o, tw, lane);
#pragma unroll
                for (int r2 = 0; r2 < 5; r2++){
                    float x, y; upk2(o[r2], x, y);
                    sm1w[wid * 800 + (r2 + 5 * tw.k1) * 5 + yr] = __floats2half2_rn(x, y);
                }
            }
            __syncthreads();

#pragma unroll 1
            for (int i = threadIdx.x; i < 1280; i += 256){
                int d = i / 160;
                int x = i - d * 160;
                const __half2* p = &sm1w[d * 800 + x * 5];
                uint4 val;
                val.x = *(const unsigned*)&p[0];
                val.y = *(const unsigned*)&p[1];
                val.z = *(const unsigned*)&p[2];
                val.w = *(const unsigned*)&p[3];
                *(uint4*)&g_tmp_h[2][k * 8 + d][x][yb * 4] = val;
            }
        }
        __syncthreads();
    }
}

// Persistent pass 2: grid(SPEC_GRID) x 256. 960 tiles.
__global__ void __launch_bounds__(256)
pass2_kernel()
{
    int wid  = threadIdx.x >> 5;
    int lane = threadIdx.x & 31;

    Tw tw; make_tw(tw, lane);

    __shared__ __half2 sm2[GS * 65];

#pragma unroll 1
    for (int tile = blockIdx.x; tile < 960; tile += SPEC_GRID){
        int t  = tile / 320;
        int rr = tile - t * 320;
        int kb = rr / 20;
        int wb = rr - kb * 20;
        int kd = kb * 8 + wid;

#pragma unroll 1
        for (int ww = 0; ww < 8; ww++){
            const __half2* src = &g_tmp_h[t][kd][wb * 8 + ww][0];
            u64p v[5], o[5];
#pragma unroll
            for (int j = 0; j < 5; j++){
                float2 f = __half22float2(src[lane + 32 * j]);
                v[j] = pk2(f.x, f.y);
            }
            fft160p(v, o, tw, lane);
#pragma unroll
            for (int r2 = 0; r2 < 5; r2++){
                float x, y; upk2(o[r2], x, y);
                sm2[(r2 + 5 * tw.k1) * 65 + ww * 8 + wid] = __floats2half2_rn(x, y);
            }
        }
        __syncthreads();

#pragma unroll 1
        for (int idx = threadIdx.x; idx < GS * 16; idx += 256){
            int h = idx >> 4, rem = idx & 15, ww = rem >> 1, q = rem & 1;
            const __half2* p = &sm2[h * 65 + ww * 8 + q * 4];
            uint4 val;
            val.x = *(const unsigned*)&p[0];
            val.y = *(const unsigned*)&p[1];
            val.z = *(const unsigned*)&p[2];
            val.w = *(const unsigned*)&p[3];
            *(uint4*)&g_field_h[t][h][wb * 8 + ww][kb * 8 + q * 4] = val;
        }
        __syncthreads();
    }
}

// ---------------- point reorder (morton counting sort) ----------------

__device__ __forceinline__ unsigned mort4(unsigned a){
    // spread 4 bits to positions 0,3,6,9
    return (a & 1u) | ((a & 2u) << 2) | ((a & 4u) << 4) | ((a & 8u) << 6);
}

__global__ void zero_hist_kernel(){
    int i = blockIdx.x * 256 + threadIdx.x;
    if (i < NBKT) g_hist[i] = 0;
}

__global__ void key_count_kernel(const float* __restrict__ xyz,
                                 const float* __restrict__ boundp, int npts){
    int i = blockIdx.x * 256 + threadIdx.x;
    if (i >= npts) return;
    float invb = 1.0f / boundp[0];
    unsigned q[3];
#pragma unroll
    for (int a = 0; a < 3; a++){
        float c = xyz[3*i + a] * invb;
        float u = (c + 1.0f) * 0.5f;
        u = fminf(fmaxf(u, 0.0f), 0.999999f);
        q[a] = (unsigned)(u * 16.0f);
    }
    unsigned key = mort4(q[0]) | (mort4(q[1]) << 1) | (mort4(q[2]) << 2);
    g_keybuf[i] = (unsigned short)key;
    atomicAdd(&g_hist[key], 1);
}

__global__ void __launch_bounds__(1024)
scan_kernel(){
    __shared__ int sh[NBKT];
    __shared__ int bs[1024];
    int t = threadIdx.x;
#pragma unroll
    for (int j = t; j < NBKT; j += 1024) sh[j] = g_hist[j];
    __syncthreads();
    int v0 = sh[4*t], v1 = sh[4*t+1], v2 = sh[4*t+2], v3 = sh[4*t+3];
    int tot = v0 + v1 + v2 + v3;
    bs[t] = tot;
    __syncthreads();
    for (int off = 1; off < 1024; off <<= 1){
        int v = (t >= off) ? bs[t - off] : 0;
        __syncthreads();
        bs[t] += v;
        __syncthreads();
    }
    int ex = bs[t] - tot;
    g_cursor[4*t]     = ex;
    g_cursor[4*t + 1] = ex + v0;
    g_cursor[4*t + 2] = ex + v0 + v1;
    g_cursor[4*t + 3] = ex + v0 + v1 + v2;
}

__global__ void scatter_kernel(int npts){
    int i = blockIdx.x * 256 + threadIdx.x;
    if (i >= npts) return;
    int key = (int)g_keybuf[i];
    int pos = atomicAdd(&g_cursor[key], 1);
    g_order[pos] = i;
}

// Sample: 16 lanes per point (2 points/warp), dense cell loads, morton order.
__global__ void __launch_bounds__(256)
sample_kernel(const float* __restrict__ xyz,
              const float* __restrict__ boundp,
              float* __restrict__ out, int npts)
{
    int warp_g = (int)((blockIdx.x * (unsigned)blockDim.x + threadIdx.x) >> 5);
    int lane = threadIdx.x & 31;
    int sub  = lane >> 4;
    int sl   = lane & 15;
    int slot = warp_g * 2 + sub;
    if (slot >= npts) return;
    int gw = g_order[slot];

    float invb = 1.0f / boundp[0];
    float p[3];
    p[0] = xyz[3*gw + 0] * invb;
    p[1] = xyz[3*gw + 1] * invb;
    p[2] = xyz[3*gw + 2] * invb;

    float wa0[3], wa1[3];
    int   c0i[3], c1i[3];
#pragma unroll
    for (int a = 0; a < 3; a++){
        float ia = (p[a] + 1.0f) * 0.5f * 159.0f;
        float fl = floorf(ia);
        float w  = ia - fl;
        int i0 = (int)fl, i1 = i0 + 1;
        float v0 = (i0 >= 0 && i0 <= 159) ? 1.0f : 0.0f;
        float v1 = (i1 >= 0 && i1 <= 159) ? 1.0f : 0.0f;
        c0i[a] = max(0, min(159, i0));
        c1i[a] = max(0, min(159, i1));
        wa0[a] = (1.0f - w) * v0;
        wa1[a] = w * v1;
    }

    const __half2* fld = &g_field_h[0][0][0][0];
    bool hi = (sl & 1) != 0;
    float gacc0 = 0.0f, gacc1 = 0.0f;

#pragma unroll
    for (int t = 0; t < 3; t++){
        const int ax = (t == 2) ? 0 : 2;
        const int ay = (t == 1) ? 0 : 1;

        __half2 w00h = __float2half2_rn(wa0[ax] * wa0[ay]);
        __half2 w01h = __float2half2_rn(wa1[ax] * wa0[ay]);
        __half2 w10h = __float2half2_rn(wa0[ax] * wa1[ay]);
        __half2 w11h = __float2half2_rn(wa1[ax] * wa1[ay]);

        int i0 = c0i[ax], i1 = c1i[ax];
        int j0 = c0i[ay], j1 = c1i[ay];

        const __half2* bp = fld + t * GS * GS * KD;
        const uint4* q00 = (const uint4*)(bp + (j0 * GS + i0) * KD) + sl;
        const uint4* q01 = (const uint4*)(bp + (j0 * GS + i1) * KD) + sl;
        const uint4* q10 = (const uint4*)(bp + (j1 * GS + i0) * KD) + sl;
        const uint4* q11 = (const uint4*)(bp + (j1 * GS + i1) * KD) + sl;

        float xt = (p[t] + 1.0f) * 0.5f;
        float s1, c1;
        sincospif(2.0f * xt, &s1, &c1);
        float cd[8], sd[8];
        cd[0] = 1.0f; sd[0] = 0.0f;
        float cc = c1, ss = s1;
        cd[1] = 2.0f * cc; sd[1] = 2.0f * ss;
#pragma unroll
        for (int j = 2; j < 8; j++){
            float nc = cc * cc - ss * ss;
            float ns = 2.0f * cc * ss;
            cc = nc; ss = ns;
            cd[j] = 2.0f * cc; sd[j] = 2.0f * ss;
        }
        float cs0 = hi ? cd[4] : cd[0], ss0 = hi ? sd[4] : sd[0];
        float cs1 = hi ? cd[5] : cd[1], ss1 = hi ? sd[5] : sd[1];
        float cs2 = hi ? cd[6] : cd[2], ss2 = hi ? sd[6] : sd[2];
        float cs3 = hi ? cd[7] : cd[3], ss3 = hi ? sd[7] : sd[3];

#pragma unroll
        for (int g = 0; g < 2; g++){
            uint4 u00 = q00[g * 16], u01 = q01[g * 16];
            uint4 u10 = q10[g * 16], u11 = q11[g * 16];
            float acc_s = 0.0f;
#pragma unroll
            for (int c = 0; c < 4; c++){
                __half2 acc = __hmul2(*(__half2*)&((&u00.x)[c]), w00h);
                acc = __hfma2(*(__half2*)&((&u01.x)[c]), w01h, acc);
                acc = __hfma2(*(__half2*)&((&u10.x)[c]), w10h, acc);
                acc = __hfma2(*(__half2*)&((&u11.x)[c]), w11h, acc);
                float2 f = __half22float2(acc);
                float csv = (c == 0) ? cs0 : (c == 1) ? cs1 : (c == 2) ? cs2 : cs3;
                float ssv = (c == 0) ? ss0 : (c == 1) ? ss1 : (c == 2) ? ss2 : ss3;
                acc_s += f.x * csv - f.y * ssv;
            }
            if (g == 0) gacc0 += acc_s; else gacc1 += acc_s;
        }
    }

    gacc0 += __shfl_xor_sync(0xffffffffu, gacc0, 1);
    gacc1 += __shfl_xor_sync(0xffffffffu, gacc1, 1);
    int  kout = hi ? (8 + (sl >> 1)) : (sl >> 1);
    float val = (hi ? gacc1 : gacc0) * INV_FSCALE;
    out[gw * NKS + kout] = val;
}

extern "C" void kernel_launch(void* const* d_in, const int* in_sizes, int n_in,
                              void* d_out, int out_size)
{
    const float* xyz   = (const float*)d_in[0];
    const float* bound = (const float*)d_in[1];
    const float* alpha = (const float*)d_in[2];
    const float* pur   = (const float*)d_in[3];
    const float* pui   = (const float*)d_in[4];
    const float* pvr   = (const float*)d_in[5];
    const float* pvi   = (const float*)d_in[6];
    const float* pwr   = (const float*)d_in[7];
    const float* pwi   = (const float*)d_in[8];

    int npts = in_sizes[0] / 3;
    int pblocks = (npts + 255) / 256;

    // reorder pipeline (independent of field)
    zero_hist_kernel<<<(NBKT + 255) / 256, 256>>>();
    key_count_kernel<<<pblocks, 256>>>(xyz, bound, npts);

    pass1_kernel<<<SPEC_GRID, 256>>>(pur, pui, pvr, pvi, pwr, pwi, alpha);

    scan_kernel<<<1, 1024>>>();
    scatter_kernel<<<pblocks, 256>>>(npts);

    pass2_kernel<<<SPEC_GRID, 256>>>();

    int nwarps = (npts + 1) / 2;
    int nblocks = (nwarps * 32 + 255) / 256;
    sample_kernel<<<nblocks, 256>>>(xyz, bound, (float*)d_out, npts);
}

// round 12
// speedup vs baseline: 1.1575x; 1.1575x over previous
#include <cuda_runtime.h>
#include <cuda_fp16.h>
#include <math.h>

#define GS   160
#define KD   128
#define NKS  16
#define FSCALE      262144.0f            // 2^18
#define INV_FSCALE  3.814697265625e-06f  // 2^-18

#define SPEC_GRID 608                    // 4 blocks/SM x 152 SMs (GB300)

__device__ __half2 g_tmp_h[3][KD][GS][GS];     // [t][kd][a_k][b]
__device__ __half2 g_field_h[3][GS][GS][KD];   // [t][h][w][kd]

// ---------------- packed f32x2 helpers (sm_103a) ----------------
typedef unsigned long long u64p;

__device__ __forceinline__ u64p pk2(float x, float y){
    u64p r; asm("mov.b64 %0, {%1, %2};" : "=l"(r) : "f"(x), "f"(y)); return r;
}
__device__ __forceinline__ void upk2(u64p p, float& x, float& y){
    asm("mov.b64 {%0, %1}, %2;" : "=f"(x), "=f"(y) : "l"(p));
}
__device__ __forceinline__ u64p swp2(u64p p){
    float x, y; upk2(p, x, y); return pk2(y, x);
}
__device__ __forceinline__ u64p fma2p(u64p a, u64p b, u64p c){
    u64p d; asm("fma.rn.f32x2 %0, %1, %2, %3;" : "=l"(d) : "l"(a), "l"(b), "l"(c)); return d;
}
__device__ __forceinline__ u64p mul2p(u64p a, u64p b){
    u64p d; asm("mul.rn.f32x2 %0, %1, %2;" : "=l"(d) : "l"(a), "l"(b)); return d;
}
__device__ __forceinline__ u64p add2p(u64p a, u64p b){
    u64p d; asm("add.rn.f32x2 %0, %1, %2;" : "=l"(d) : "l"(a), "l"(b)); return d;
}
__device__ __forceinline__ u64p cmulp(u64p T, u64p tc, u64p ts){
    return fma2p(swp2(T), ts, mul2p(T, tc));
}

struct Tw {
    u64p stc[5], sts[5], g2[5];
    u64p tac[4], tas[4];
    int  k1;
};

__device__ __forceinline__ float softplus_scale(const float* __restrict__ alpha_params){
    float a0 = alpha_params[0];
    float bx = 10.0f * a0;
    float alpha = (bx > 1.0f) ? a0 : (log1pf(expf(fminf(bx, 1.0f))) * 0.1f);
    return alpha * (1.0f / 25600.0f) * FSCALE;
}

__device__ __forceinline__ void make_tw(Tw &tw, int lane){
#pragma unroll
    for (int s = 0; s < 5; s++){
        int H = 16 >> s;
        float cv = 1.0f, sv = 0.0f, g = 1.0f;
        if (lane & H){
            int j = lane & (H - 1);
            sincospif((float)j / (float)H, &sv, &cv);
            g = -1.0f;
        }
        tw.stc[s] = pk2(cv, cv);
        tw.sts[s] = pk2(-sv, sv);
        tw.g2[s]  = pk2(g, g);
    }
    tw.k1 = (int)(__brev((unsigned)lane) >> 27);
#pragma unroll
    for (int r = 1; r < 5; r++){
        float sv, cv;
        sincospif((float)(lane * r) / 80.0f, &sv, &cv);
        tw.tac[r - 1] = pk2(cv, cv);
        tw.tas[r - 1] = pk2(-sv, sv);
    }
}

// Inverse-sign DFT-160 across a warp, stride-1 input mapping, packed f32x2.
__device__ __forceinline__ void fft160p(u64p v[5], u64p o[5], const Tw &tw, int lane){
    const float C1 =  0.30901699437494745f;
    const float C2 = -0.80901699437494734f;
    const float S1 =  0.95105651629515353f;
    const float S2 =  0.58778525229247314f;
    const u64p C1p  = pk2(C1, C1),  C2p = pk2(C2, C2);
    const u64p S1p  = pk2(S1, S1),  S2p = pk2(S2, S2);
    const u64p mS1p = pk2(-S1, -S1);
    const u64p NEG1 = pk2(-1.0f, -1.0f);
    const u64p PM   = pk2(-1.0f, 1.0f);
    const u64p MP   = pk2(1.0f, -1.0f);

    u64p s1 = add2p(v[1], v[4]);
    u64p d1 = fma2p(v[4], NEG1, v[1]);
    u64p s2 = add2p(v[2], v[3]);
    u64p d2 = fma2p(v[3], NEG1, v[2]);
    o[0] = add2p(v[0], add2p(s1, s2));
    u64p ua = fma2p(s2, C2p, fma2p(s1, C1p, v[0]));
    u64p ub = fma2p(s2, C1p, fma2p(s1, C2p, v[0]));
    u64p wa = fma2p(d2, S2p,  mul2p(d1, S1p));
    u64p wb = fma2p(d2, mS1p, mul2p(d1, S2p));
    u64p X1 = fma2p(swp2(wa), PM, ua);
    u64p X4 = fma2p(swp2(wa), MP, ua);
    u64p X2 = fma2p(swp2(wb), PM, ub);
    u64p X3 = fma2p(swp2(wb), MP, ub);
    o[1] = cmulp(X1, tw.tac[0], tw.tas[0]);
    o[2] = cmulp(X2, tw.tac[1], tw.tas[1]);
    o[3] = cmulp(X3, tw.tac[2], tw.tas[2]);
    o[4] = cmulp(X4, tw.tac[3], tw.tas[3]);

#pragma unroll
    for (int s = 0; s < 5; s++){
        int H = 16 >> s;
#pragma unroll
        for (int r = 0; r < 5; r++){
            float ox, oy; upk2(o[r], ox, oy);
            float px = __shfl_xor_sync(0xffffffffu, ox, H);
            float py = __shfl_xor_sync(0xffffffffu, oy, H);
            u64p T = fma2p(o[r], tw.g2[s], pk2(px, py));
            o[r] = cmulp(T, tw.stc[s], tw.sts[s]);
        }
    }
}

// Persistent pass 1: grid(SPEC_GRID) x 256. 1920 tiles (640 per tensor).
__global__ void __launch_bounds__(256)
pass1_kernel(const float* __restrict__ pur, const float* __restrict__ pui,
             const float* __restrict__ pvr, const float* __restrict__ pvi,
             const float* __restrict__ pwr, const float* __restrict__ pwi,
             const float* __restrict__ alpha_params)
{
    __shared__ char smbuf[48640];
    int wid  = threadIdx.x >> 5;
    int lane = threadIdx.x & 31;
    float scale = softplus_scale(alpha_params);

    Tw tw; make_tw(tw, lane);

#pragma unroll 1
    for (int tile = blockIdx.x; tile < 1920; tile += SPEC_GRID){
        int z  = tile / 640;
        int id = tile - z * 640;

        if (z < 2){
            int kd = id / 5;
            int bx = id - kd * 5;
            const float* re = (z == 0) ? pur : pvr;
            const float* im = (z == 0) ? pui : pvi;
            int k = kd >> 3, d = kd & 7;

            __half2* sm1 = (__half2*)smbuf;

#pragma unroll 1
            for (int r = 0; r < 4; r++){
                int rl = wid * 4 + r;
                int b  = bx * 32 + rl;
                int base = (z == 0) ? ((kd * GS + b) * GS)
                                    : (((k * GS + b) * 8 + d) * GS);
                u64p v[5], o[5];
#pragma unroll
                for (int j = 0; j < 5; j++){
                    int idx = base + lane + 32 * j;
                    v[j] = pk2(re[idx] * scale, im[idx] * scale);
                }
                fft160p(v, o, tw, lane);
#pragma unroll
                for (int r2 = 0; r2 < 5; r2++){
                    float x, y; upk2(o[r2], x, y);
                    sm1[(r2 + 5 * tw.k1) * 33 + rl] = __floats2half2_rn(x, y);
                }
            }
            __syncthreads();

#pragma unroll 1
            for (int idx = threadIdx.x; idx < GS * 8; idx += 256){
                int w = idx >> 3, g = idx & 7;
                const __half2* p = &sm1[w * 33 + g * 4];
                uint4 val;
                val.x = *(const unsigned*)&p[0];
                val.y = *(const unsigned*)&p[1];
                val.z = *(const unsigned*)&p[2];
                val.w = *(const unsigned*)&p[3];
                *(uint4*)&g_tmp_h[z][kd][w][bx * 32 + g * 4] = val;
            }
        } else {
            int k  = id / 40;
            int yb = id - k * 40;

            unsigned* smw  = (unsigned*)smbuf;
            __half2*  sm1w = (__half2*)(smbuf + 4 * 1440 * 4);

            {
                const float4* re4 = (const float4*)pwr;
                const float4* im4 = (const float4*)pwi;
                int y0 = yb * 4;
#pragma unroll 1
                for (int i = threadIdx.x; i < 1280; i += 256){
                    int X   = i >> 3;
                    int rem = i & 7;
                    int y   = rem >> 1;
                    int dg  = (rem & 1) * 4;
                    int gidx = ((k * GS + X) * GS + y0 + y) * 2 + (rem & 1);
                    float4 fr = re4[gidx];
                    float4 fi = im4[gidx];
                    unsigned* dst = &smw[y * 1440 + X * 9 + dg];
                    __half2 h0 = __floats2half2_rn(fr.x * scale, fi.x * scale);
                    __half2 h1 = __floats2half2_rn(fr.y * scale, fi.y * scale);
                    __half2 h2 = __floats2half2_rn(fr.z * scale, fi.z * scale);
                    __half2 h3 = __floats2half2_rn(fr.w * scale, fi.w * scale);
                    dst[0] = *(unsigned*)&h0;
                    dst[1] = *(unsigned*)&h1;
                    dst[2] = *(unsigned*)&h2;
                    dst[3] = *(unsigned*)&h3;
                }
            }
            __syncthreads();

#pragma unroll 1
            for (int yr = 0; yr < 4; yr++){
                u64p v[5], o[5];
#pragma unroll
                for (int j = 0; j < 5; j++){
                    unsigned u = smw[yr * 1440 + (lane + 32 * j) * 9 + wid];
                    float2 f = __half22float2(*(__half2*)&u);
                    v[j] = pk2(f.x, f.y);
                }
                fft160p(v, o, tw, lane);
#pragma unroll
                for (int r2 = 0; r2 < 5; r2++){
                    float x, y; upk2(o[r2], x, y);
                    sm1w[wid * 800 + (r2 + 5 * tw.k1) * 5 + yr] = __floats2half2_rn(x, y);
                }
            }
            __syncthreads();

#pragma unroll 1
            for (int i = threadIdx.x; i < 1280; i += 256){
                int d = i / 160;
                int x = i - d * 160;
                const __half2* p = &sm1w[d * 800 + x * 5];
                uint4 val;
                val.x = *(const unsigned*)&p[0];
                val.y = *(const unsigned*)&p[1];
                val.z = *(const unsigned*)&p[2];
                val.w = *(const unsigned*)&p[3];
                *(uint4*)&g_tmp_h[2][k * 8 + d][x][yb * 4] = val;
            }
        }
        __syncthreads();
    }
}

// Persistent pass 2: grid(SPEC_GRID) x 256. 960 tiles.
__global__ void __launch_bounds__(256)
pass2_kernel()
{
    int wid  = threadIdx.x >> 5;
    int lane = threadIdx.x & 31;

    Tw tw; make_tw(tw, lane);

    __shared__ __half2 sm2[GS * 65];

#pragma unroll 1
    for (int tile = blockIdx.x; tile < 960; tile += SPEC_GRID){
        int t  = tile / 320;
        int rr = tile - t * 320;
        int kb = rr / 20;
        int wb = rr - kb * 20;
        int kd = kb * 8 + wid;

#pragma unroll 1
        for (int ww = 0; ww < 8; ww++){
            const __half2* src = &g_tmp_h[t][kd][wb * 8 + ww][0];
            u64p v[5], o[5];
#pragma unroll
            for (int j = 0; j < 5; j++){
                float2 f = __half22float2(src[lane + 32 * j]);
                v[j] = pk2(f.x, f.y);
            }
            fft160p(v, o, tw, lane);
#pragma unroll
            for (int r2 = 0; r2 < 5; r2++){
                float x, y; upk2(o[r2], x, y);
                sm2[(r2 + 5 * tw.k1) * 65 + ww * 8 + wid] = __floats2half2_rn(x, y);
            }
        }
        __syncthreads();

#pragma unroll 1
        for (int idx = threadIdx.x; idx < GS * 16; idx += 256){
            int h = idx >> 4, rem = idx & 15, ww = rem >> 1, q = rem & 1;
            const __half2* p = &sm2[h * 65 + ww * 8 + q * 4];
            uint4 val;
            val.x = *(const unsigned*)&p[0];
            val.y = *(const unsigned*)&p[1];
            val.z = *(const unsigned*)&p[2];
            val.w = *(const unsigned*)&p[3];
            *(uint4*)&g_field_h[t][h][wb * 8 + ww][kb * 8 + q * 4] = val;
        }
        __syncthreads();
    }
}

// Sample: 8 lanes per point (4 points/warp), dense cell loads.
// Cell = 512 B = 32 uint4. Lane sl2 (0..7) reads uint4 m = sl2 + 8g, g=0..3.
// uint4 #m covers kd 4m..4m+3 -> k = 4g + (sl2>>1), d-half = (sl2&1)*4.
__global__ void __launch_bounds__(256)
sample_kernel(const float* __restrict__ xyz,
              const float* __restrict__ boundp,
              float* __restrict__ out, int npts)
{
    int warp_g = (int)((blockIdx.x * (unsigned)blockDim.x + threadIdx.x) >> 5);
    int lane = threadIdx.x & 31;
    int sub  = lane >> 3;          // point within warp (0..3)
    int sl2  = lane & 7;           // 8 lanes per point
    int gw   = warp_g * 4 + sub;
    if (gw >= npts) return;

    float invb = 1.0f / boundp[0];
    float p[3];
    p[0] = xyz[3*gw + 0] * invb;
    p[1] = xyz[3*gw + 1] * invb;
    p[2] = xyz[3*gw + 2] * invb;

    float wa0[3], wa1[3];
    int   c0i[3], c1i[3];
#pragma unroll
    for (int a = 0; a < 3; a++){
        float ia = (p[a] + 1.0f) * 0.5f * 159.0f;
        float fl = floorf(ia);
        float w  = ia - fl;
        int i0 = (int)fl, i1 = i0 + 1;
        float v0 = (i0 >= 0 && i0 <= 159) ? 1.0f : 0.0f;
        float v1 = (i1 >= 0 && i1 <= 159) ? 1.0f : 0.0f;
        c0i[a] = max(0, min(159, i0));
        c1i[a] = max(0, min(159, i1));
        wa0[a] = (1.0f - w) * v0;
        wa1[a] = w * v1;
    }

    const __half2* fld = &g_field_h[0][0][0][0];
    bool hi = (sl2 & 1) != 0;
    float acc0 = 0.0f, acc1 = 0.0f, acc2 = 0.0f, acc3 = 0.0f;

#pragma unroll
    for (int t = 0; t < 3; t++){
        const int ax = (t == 2) ? 0 : 2;
        const int ay = (t == 1) ? 0 : 1;

        __half2 w00h = __float2half2_rn(wa0[ax] * wa0[ay]);
        __half2 w01h = __float2half2_rn(wa1[ax] * wa0[ay]);
        __half2 w10h = __float2half2_rn(wa0[ax] * wa1[ay]);
        __half2 w11h = __float2half2_rn(wa1[ax] * wa1[ay]);

        int i0 = c0i[ax], i1 = c1i[ax];
        int j0 = c0i[ay], j1 = c1i[ay];

        const __half2* bp = fld + t * GS * GS * KD;
        const uint4* q00 = (const uint4*)(bp + (j0 * GS + i0) * KD) + sl2;
        const uint4* q01 = (const uint4*)(bp + (j0 * GS + i1) * KD) + sl2;
        const uint4* q10 = (const uint4*)(bp + (j1 * GS + i0) * KD) + sl2;
        const uint4* q11 = (const uint4*)(bp + (j1 * GS + i1) * KD) + sl2;

        float xt = (p[t] + 1.0f) * 0.5f;
        float s1, c1;
        sincospif(2.0f * xt, &s1, &c1);
        float cd[8], sd[8];
        cd[0] = 1.0f; sd[0] = 0.0f;
        float cc = c1, ss = s1;
        cd[1] = 2.0f * cc; sd[1] = 2.0f * ss;
#pragma unroll
        for (int j = 2; j < 8; j++){
            float nc = cc * cc - ss * ss;
            float ns = 2.0f * cc * ss;
            cc = nc; ss = ns;
            cd[j] = 2.0f * cc; sd[j] = 2.0f * ss;
        }
        float cs0 = hi ? cd[4] : cd[0], ss0 = hi ? sd[4] : sd[0];
        float cs1 = hi ? cd[5] : cd[1], ss1 = hi ? sd[5] : sd[1];
        float cs2 = hi ? cd[6] : cd[2], ss2 = hi ? sd[6] : sd[2];
        float cs3 = hi ? cd[7] : cd[3], ss3 = hi ? sd[7] : sd[3];

#pragma unroll 2
        for (int g = 0; g < 4; g++){
            uint4 u00 = q00[g * 8], u01 = q01[g * 8];
            uint4 u10 = q10[g * 8], u11 = q11[g * 8];
            float acc_s = 0.0f;
#pragma unroll
            for (int c = 0; c < 4; c++){
                __half2 acc = __hmul2(*(__half2*)&((&u00.x)[c]), w00h);
                acc = __hfma2(*(__half2*)&((&u01.x)[c]), w01h, acc);
                acc = __hfma2(*(__half2*)&((&u10.x)[c]), w10h, acc);
                acc = __hfma2(*(__half2*)&((&u11.x)[c]), w11h, acc);
                float2 f = __half22float2(acc);
                float csv = (c == 0) ? cs0 : (c == 1) ? cs1 : (c == 2) ? cs2 : cs3;
                float ssv = (c == 0) ? ss0 : (c == 1) ? ss1 : (c == 2) ? ss2 : ss3;
                acc_s += f.x * csv - f.y * ssv;
            }
            if      (g == 0) acc0 += acc_s;
            else if (g == 1) acc1 += acc_s;
            else if (g == 2) acc2 += acc_s;
            else             acc3 += acc_s;
        }
    }

    // pair-reduce: lanes sl2 and sl2^1 hold the two d-halves of the same 4 k's
    acc0 += __shfl_xor_sync(0xffffffffu, acc0, 1);
    acc1 += __shfl_xor_sync(0xffffffffu, acc1, 1);
    acc2 += __shfl_xor_sync(0xffffffffu, acc2, 1);
    acc3 += __shfl_xor_sync(0xffffffffu, acc3, 1);

    int q = sl2 >> 1;                 // 0..3
    float* po = out + gw * NKS;
    if (!hi){
        po[q]      = acc0 * INV_FSCALE;   // k = q
        po[4 + q]  = acc1 * INV_FSCALE;   // k = 4+q
    } else {
        po[8 + q]  = acc2 * INV_FSCALE;   // k = 8+q
        po[12 + q] = acc3 * INV_FSCALE;   // k = 12+q
    }
}

extern "C" void kernel_launch(void* const* d_in, const int* in_sizes, int n_in,
                              void* d_out, int out_size)
{
    const float* xyz   = (const float*)d_in[0];
    const float* bound = (const float*)d_in[1];
    const float* alpha = (const float*)d_in[2];
    const float* pur   = (const float*)d_in[3];
    const float* pui   = (const float*)d_in[4];
    const float* pvr   = (const float*)d_in[5];
    const float* pvi   = (const float*)d_in[6];
    const float* pwr   = (const float*)d_in[7];
    const float* pwi   = (const float*)d_in[8];

    pass1_kernel<<<SPEC_GRID, 256>>>(pur, pui, pvr, pvi, pwr, pwi, alpha);
    pass2_kernel<<<SPEC_GRID, 256>>>();

    int npts = in_sizes[0] / 3;
    int nwarps = (npts + 3) / 4;
    int nblocks = (nwarps * 32 + 255) / 256;
    sample_kernel<<<nblocks, 256>>>(xyz, bound, (float*)d_out, npts);
}